// round 4
// baseline (speedup 1.0000x reference)
#include <cuda_runtime.h>
#include <math.h>
#include <math_constants.h>

#define BGRAPH 8
#define PPTS   4096
#define KNN    20
#define LCOV   10
#define FDIM   32
#define KSS    5
#define NCLS   40
#define NTOT   (BGRAPH*PPTS)      // 32768
#define NGROUP 24
#define HID    256

#define T1     128
#define BLK1   (NTOT/T1)          // 256 blocks, 32 per graph
#define TILES1 (PPTS/T1)          // 32
#define T2     256
#define BLK2   (NTOT/T2)          // 128

// ---------------- scratch (device globals; no allocation) ----------------
__device__ float g_node[NTOT*FDIM];     // 4 MB node features
__device__ float g_nrm [NTOT*3];        // normals (v3)
__device__ float g_bnpart[BLK1*64];     // per-block sum / sumsq
__device__ float g_bnfin[64];           // scale[32], shift[32]
__device__ float g_yspart[BLK2*64];     // per-block ys partials (lo/hi group)

// ---------------- helpers ----------------
__device__ __forceinline__ void power_iter5(
    float a00,float a01,float a02,float a11,float a12,float a22,
    float& vx,float& vy,float& vz,float& lam)
{
    float x=0.57735026919f, y=0.57735026919f, z=0.57735026919f;
    #pragma unroll
    for (int it=0; it<5; ++it){
        float nx = a00*x + a01*y + a02*z;
        float ny = a01*x + a11*y + a12*z;
        float nz = a02*x + a12*y + a22*z;
        float nrm = sqrtf(nx*nx+ny*ny+nz*nz) + 1e-12f;
        x = nx/nrm; y = ny/nrm; z = nz/nrm;
    }
    float mx = a00*x + a01*y + a02*z;
    float my = a01*x + a11*y + a12*z;
    float mz = a02*x + a12*y + a22*z;
    lam = x*mx + y*my + z*mz;
    vx=x; vy=y; vz=z;
}

// ============ kernel 1: KNN + eig + dirc + SplineConv + BN partials ============
__global__ __launch_bounds__(T1)
void k1_geom(const float* __restrict__ pos,
             const float* __restrict__ Wsp,
             const float* __restrict__ root,
             const float* __restrict__ bias)
{
    extern __shared__ float sp[];           // 12288 floats = 48KB (graph positions)
    const int tid  = threadIdx.x;
    const int b    = blockIdx.x / TILES1;
    const int tile = blockIdx.x % TILES1;

    // load this graph's positions into smem (float4-vectorized)
    {
        const float4* gp = (const float4*)(pos + (size_t)b*PPTS*3);
        for (int i = tid; i < PPTS*3/4; i += T1) ((float4*)sp)[i] = gp[i];
    }
    __syncthreads();

    const int ql = tile*T1 + tid;           // local query index in graph
    const int n  = b*PPTS + ql;             // global node id
    const float qx = sp[3*ql+0], qy = sp[3*ql+1], qz = sp[3*ql+2];

    // ---- top-20 nearest (registers, sorted ascending) ----
    float bd[KNN]; int bi[KNN];
    #pragma unroll
    for (int s=0;s<KNN;s++){ bd[s]=CUDART_INF_F; bi[s]=0; }

    #pragma unroll 4
    for (int j = 0; j < PPTS; ++j) {
        float dx = sp[3*j+0]-qx, dy = sp[3*j+1]-qy, dz = sp[3*j+2]-qz;
        float d  = fmaf(dx,dx,fmaf(dy,dy,dz*dz));
        if (j == ql) d = CUDART_INF_F;
        if (d < bd[KNN-1]) {
            float cd=d; int ci=j;
            #pragma unroll
            for (int s=0;s<KNN;s++){
                if (cd < bd[s]) {
                    float td=bd[s]; bd[s]=cd; cd=td;
                    int   ti=bi[s]; bi[s]=ci; ci=ti;
                }
            }
        }
    }

    // ---- covariance of nearest 10 offsets ----
    float cxx=0.f,cxy=0.f,cxz=0.f,cyy=0.f,cyz=0.f,czz=0.f;
    #pragma unroll
    for (int m=0;m<LCOV;m++){
        int j=bi[m];
        float dx=sp[3*j+0]-qx, dy=sp[3*j+1]-qy, dz=sp[3*j+2]-qz;
        cxx=fmaf(dx,dx,cxx); cxy=fmaf(dx,dy,cxy); cxz=fmaf(dx,dz,cxz);
        cyy=fmaf(dy,dy,cyy); cyz=fmaf(dy,dz,cyz); czz=fmaf(dz,dz,czz);
    }

    // ---- eig via power iteration + deflation + cross ----
    float v1x,v1y,v1z,l1, v2x,v2y,v2z,l2;
    power_iter5(cxx,cxy,cxz,cyy,cyz,czz, v1x,v1y,v1z,l1);
    power_iter5(cxx-l1*v1x*v1x, cxy-l1*v1x*v1y, cxz-l1*v1x*v1z,
                cyy-l1*v1y*v1y, cyz-l1*v1y*v1z, czz-l1*v1z*v1z,
                v2x,v2y,v2z,l2);
    float v3x = v1y*v2z - v1z*v2y;
    float v3y = v1z*v2x - v1x*v2z;
    float v3z = v1x*v2y - v1y*v2x;
    {
        float nn = sqrtf(v3x*v3x+v3y*v3y+v3z*v3z) + 1e-12f;
        v3x/=nn; v3y/=nn; v3z/=nn;
    }

    // ---- dirc pass 1: sign + max_abs (store rotated coords to local) ----
    float dl0[KNN], dl1[KNN], dl2[KNN];
    float sumz=0.f, mxa=0.f;
    #pragma unroll
    for (int kk=0;kk<KNN;kk++){
        int j=bi[kk];
        float dx=sp[3*j+0]-qx, dy=sp[3*j+1]-qy, dz=sp[3*j+2]-qz;
        float d0 = dx*v1x+dy*v1y+dz*v1z;
        float d1 = dx*v2x+dy*v2y+dz*v2z;
        float d2 = dx*v3x+dy*v3y+dz*v3z;
        dl0[kk]=d0; dl1[kk]=d1; dl2[kk]=d2;
        sumz += d2;
        mxa = fmaxf(mxa, fmaxf(fabsf(d0), fmaxf(fabsf(d1), fabsf(d2))));
    }
    const float sgn = (sumz>0.f)?1.f:((sumz<0.f)?-1.f:0.f);

    // ---- SplineConv (degree-1, open, KS=5) ----
    float msg[FDIM];
    #pragma unroll
    for (int f=0;f<FDIM;f++) msg[f]=0.f;

    for (int kk=0;kk<KNN;kk++){
        float d0 = dl0[kk], d1 = dl1[kk], d2 = dl2[kk]*sgn;
        float p0 = (d0/mxa)*0.5f+0.5f;
        float p1 = (d1/mxa)*0.5f+0.5f;
        float p2 = (d2/mxa)*0.5f+0.5f;
        float u0 = p0*(float)(KSS-1), u1 = p1*(float)(KSS-1), u2 = p2*(float)(KSS-1);
        float f0 = floorf(u0), f1 = floorf(u1), f2 = floorf(u2);
        float r0 = u0-f0, r1 = u1-f1, r2 = u2-f2;
        int i0 = min(max((int)f0,0),KSS-1);
        int i1 = min(max((int)f1,0),KSS-1);
        int i2 = min(max((int)f2,0),KSS-1);
        #pragma unroll
        for (int s=0;s<8;s++){
            float w0 = (s&4)? r0 : 1.f-r0;
            float w1 = (s&2)? r1 : 1.f-r1;
            float w2 = (s&1)? r2 : 1.f-r2;
            float bas = w0*w1*w2;
            int ii0 = min(i0 + ((s>>2)&1), KSS-1);
            int ii1 = min(i1 + ((s>>1)&1), KSS-1);
            int ii2 = min(i2 + (s&1),      KSS-1);
            int flat = (ii0*KSS+ii1)*KSS+ii2;
            const float4* wr = (const float4*)(Wsp + flat*FDIM);
            #pragma unroll
            for (int q=0;q<FDIM/4;q++){
                float4 w = __ldg(&wr[q]);
                msg[4*q+0] = fmaf(bas,w.x,msg[4*q+0]);
                msg[4*q+1] = fmaf(bas,w.y,msg[4*q+1]);
                msg[4*q+2] = fmaf(bas,w.z,msg[4*q+2]);
                msg[4*q+3] = fmaf(bas,w.w,msg[4*q+3]);
            }
        }
    }

    // ---- node features + outputs ----
    float nodef[FDIM];
    #pragma unroll
    for (int f=0;f<FDIM;f++)
        nodef[f] = msg[f]/(float)KNN + __ldg(&root[f]) + __ldg(&bias[f]);

    {
        float4* on = (float4*)(g_node + (size_t)n*FDIM);
        #pragma unroll
        for (int q=0;q<FDIM/4;q++)
            on[q] = make_float4(nodef[4*q],nodef[4*q+1],nodef[4*q+2],nodef[4*q+3]);
        g_nrm[n*3+0]=v3x; g_nrm[n*3+1]=v3y; g_nrm[n*3+2]=v3z;
    }

    // ---- BN partial sums (block reduce; reuse pos smem after barrier) ----
    float ss[FDIM], sq[FDIM];
    #pragma unroll
    for (int f=0;f<FDIM;f++){ ss[f]=nodef[f]; sq[f]=nodef[f]*nodef[f]; }
    #pragma unroll
    for (int f=0;f<FDIM;f++){
        #pragma unroll
        for (int o=16;o>0;o>>=1){
            ss[f] += __shfl_xor_sync(0xffffffffu, ss[f], o);
            sq[f] += __shfl_xor_sync(0xffffffffu, sq[f], o);
        }
    }
    __syncthreads();                        // done with positions -> reuse sp
    float* sred = sp;                       // 4 warps * 64 floats
    int wid = tid>>5, lane = tid&31;
    if (lane==0){
        #pragma unroll
        for (int f=0;f<FDIM;f++){ sred[wid*64+f]=ss[f]; sred[wid*64+32+f]=sq[f]; }
    }
    __syncthreads();
    if (tid < 64){
        float a = sred[tid] + sred[64+tid] + sred[128+tid] + sred[192+tid];
        g_bnpart[blockIdx.x*64 + tid] = a;
    }
}

// ============ kernel 2: finalize BN stats ============
__global__ void k_bnfin(const float* __restrict__ gamma, const float* __restrict__ beta)
{
    int f = threadIdx.x;
    if (f >= FDIM) return;
    double s=0.0, q=0.0;
    for (int b=0;b<BLK1;b++){ s += (double)g_bnpart[b*64+f]; q += (double)g_bnpart[b*64+32+f]; }
    float mu  = (float)(s/(double)NTOT);
    float ex2 = (float)(q/(double)NTOT);
    float var = ex2 - mu*mu;
    float sc  = gamma[f]/sqrtf(var + 1e-5f);
    g_bnfin[f]      = sc;
    g_bnfin[32+f]   = beta[f] - mu*sc;
}

// ============ kernel 3: BN apply + sigmoid + grouped mean partials ============
__global__ __launch_bounds__(T2)
void k2_sig()
{
    __shared__ float sred[8*64];
    const int tid = threadIdx.x;
    const int n   = blockIdx.x*T2 + tid;

    float xb[FDIM];
    {
        const float4* np = (const float4*)(g_node + (size_t)n*FDIM);
        #pragma unroll
        for (int q=0;q<FDIM/4;q++){
            float4 w = np[q];
            xb[4*q+0]=w.x; xb[4*q+1]=w.y; xb[4*q+2]=w.z; xb[4*q+3]=w.w;
        }
        #pragma unroll
        for (int f=0;f<FDIM;f++) xb[f] = xb[f]*g_bnfin[f] + g_bnfin[32+f];
    }
    float vv0 = g_nrm[n*3+0], vv1 = g_nrm[n*3+1], vv2 = g_nrm[n*3+2];

    float accA[FDIM], accB[FDIM];
    #pragma unroll
    for (int j=0;j<FDIM;j++){ accA[j]=0.f; accB[j]=0.f; }

    const int base = n*96;
    const int gA   = (blockIdx.x*T2*96) >> 17;       // first group in block
    const int thr  = (gA+1) << 17;                   // boundary flat index

    #pragma unroll
    for (int m=0;m<96;m++){
        const int f = m/3, c = m-3*f, j = m&31;
        float vc = (c==0)? vv0 : ((c==1)? vv1 : vv2);
        float a  = xb[f]*vc;
        float y  = 1.f/(1.f + expf(-a));
        if (base + m >= thr) accB[j] += y; else accA[j] += y;
    }

    #pragma unroll
    for (int j=0;j<FDIM;j++){
        #pragma unroll
        for (int o=16;o>0;o>>=1){
            accA[j] += __shfl_xor_sync(0xffffffffu, accA[j], o);
            accB[j] += __shfl_xor_sync(0xffffffffu, accB[j], o);
        }
    }
    int wid = tid>>5, lane = tid&31;
    if (lane==0){
        #pragma unroll
        for (int j=0;j<FDIM;j++){ sred[wid*64+j]=accA[j]; sred[wid*64+32+j]=accB[j]; }
    }
    __syncthreads();
    if (tid < 64){
        float a = 0.f;
        #pragma unroll
        for (int w=0;w<8;w++) a += sred[w*64+tid];
        g_yspart[blockIdx.x*64 + tid] = a;
    }
}

// ============ kernel 4: fold partials + MLP + log_softmax ============
__global__ __launch_bounds__(256)
void k3_head(const float* __restrict__ W1, const float* __restrict__ b1,
             const float* __restrict__ W2, const float* __restrict__ b2,
             float* __restrict__ out)
{
    __shared__ float ys[NGROUP*FDIM];    // 768
    __shared__ float y1[NGROUP*HID];     // 6144
    __shared__ float zs[NGROUP*NCLS];    // 960
    __shared__ float ls[NGROUP];
    const int tid = threadIdx.x;

    for (int idx = tid; idx < NGROUP*FDIM; idx += 256){
        const int g = idx>>5, j = idx&31;
        float s = 0.f;
        for (int bb=0; bb<BLK2; bb++){
            const int gA = (bb*T2*96) >> 17;
            if (gA   == g) s += g_yspart[bb*64 + j];
            if (gA+1 == g) s += g_yspart[bb*64 + 32 + j];
        }
        ys[idx] = s / 4096.f;
    }
    __syncthreads();

    // layer 1: (24,32)@(32,256) + elu
    {
        const int h = tid;   // HID == 256 == blockDim
        for (int g=0; g<NGROUP; g++){
            float d = b1[h];
            #pragma unroll
            for (int f=0; f<FDIM; f++) d = fmaf(ys[g*FDIM+f], W1[f*HID+h], d);
            y1[g*HID+h] = (d > 0.f) ? d : expm1f(d);
        }
    }
    __syncthreads();

    // layer 2: (24,256)@(256,40)
    for (int o = tid; o < NGROUP*NCLS; o += 256){
        const int g = o/NCLS, cc = o - g*NCLS;
        float d = b2[cc];
        for (int h=0; h<HID; h++) d = fmaf(y1[g*HID+h], W2[h*NCLS+cc], d);
        zs[o] = d;
    }
    __syncthreads();

    if (tid < NGROUP){
        float m = -CUDART_INF_F;
        for (int cc=0; cc<NCLS; cc++) m = fmaxf(m, zs[tid*NCLS+cc]);
        float s = 0.f;
        for (int cc=0; cc<NCLS; cc++) s += expf(zs[tid*NCLS+cc] - m);
        ls[tid] = m + logf(s);
    }
    __syncthreads();
    for (int o = tid; o < NGROUP*NCLS; o += 256)
        out[o] = zs[o] - ls[o/NCLS];
}

// ---------------- launch ----------------
extern "C" void kernel_launch(void* const* d_in, const int* in_sizes, int n_in,
                              void* d_out, int out_size)
{
    const float* pos   = (const float*)d_in[0];
    const float* Wsp   = (const float*)d_in[1];
    const float* root  = (const float*)d_in[2];
    const float* bias  = (const float*)d_in[3];
    const float* gamma = (const float*)d_in[4];
    const float* beta  = (const float*)d_in[5];
    const float* W1    = (const float*)d_in[6];
    const float* b1    = (const float*)d_in[7];
    const float* W2    = (const float*)d_in[8];
    const float* b2    = (const float*)d_in[9];
    float* out = (float*)d_out;

    const size_t smem1 = (size_t)PPTS*3*sizeof(float);   // 49152 bytes (default limit, no attribute needed)
    k1_geom<<<BLK1, T1, smem1>>>(pos, Wsp, root, bias);
    k_bnfin<<<1, 32>>>(gamma, beta);
    k2_sig<<<BLK2, T2>>>();
    k3_head<<<1, 256>>>(W1, b1, W2, b2, out);
}

// round 8
// speedup vs baseline: 2.7976x; 2.7976x over previous
#include <cuda_runtime.h>
#include <math.h>
#include <math_constants.h>

typedef unsigned int u32;

#define BGRAPH 8
#define PPTS   4096
#define KNN    20
#define LCOV   10
#define FDIM   32
#define KSS    5
#define NCLS   40
#define NTOT   (BGRAPH*PPTS)      // 32768
#define NGROUP 24
#define HID    256

#define T1     128
#define BLK1   (NTOT/T1)          // 256 geom blocks, 32 per graph
#define TILES1 (PPTS/T1)          // 32
#define NSPLIT 4
#define CAND   (PPTS/NSPLIT)      // 1024 candidates per scan block
#define T2     256
#define BLK2   (NTOT/T2)          // 128

// ---------------- scratch (device globals; no allocation) ----------------
__device__ float g_node[NTOT*FDIM];          // node features
__device__ float g_nrm [NTOT*3];             // normals (v3)
__device__ float g_bnpart[BLK1*64];          // per-block sum / sumsq
__device__ float g_bnfin[64];                // scale[32], shift[32]
__device__ float g_yspart[BLK2*64];          // per-block ys partials
__device__ u32   g_part[BLK1*NSPLIT*KNN*T1]; // partial knn lists (packed keys)

// ---------------- helpers ----------------
__device__ __forceinline__ float fast_tanh(float x){
    float y; asm("tanh.approx.f32 %0, %1;" : "=f"(y) : "f"(x)); return y;
}

__device__ __forceinline__ void power_iter5(
    float a00,float a01,float a02,float a11,float a12,float a22,
    float& vx,float& vy,float& vz,float& lam)
{
    float x=0.57735026919f, y=0.57735026919f, z=0.57735026919f;
    #pragma unroll
    for (int it=0; it<5; ++it){
        float nx = a00*x + a01*y + a02*z;
        float ny = a01*x + a11*y + a12*z;
        float nz = a02*x + a12*y + a22*z;
        float nrm = sqrtf(nx*nx+ny*ny+nz*nz) + 1e-12f;
        x = nx/nrm; y = ny/nrm; z = nz/nrm;
    }
    float mx = a00*x + a01*y + a02*z;
    float my = a01*x + a11*y + a12*z;
    float mz = a02*x + a12*y + a22*z;
    lam = x*mx + y*my + z*mz;
    vx=x; vy=y; vz=z;
}

// ============ kernel 0: split KNN scan (packed u32 keys, IMNMX cascade) ============
__global__ __launch_bounds__(T1)
void k_scan(const float* __restrict__ pos)
{
    __shared__ float sp[3*CAND];                 // 12 KB candidate slab
    const int tid     = threadIdx.x;
    const int tileblk = blockIdx.x >> 2;         // 0..255
    const int split   = blockIdx.x & 3;
    const int b       = tileblk / TILES1;
    const int tile    = tileblk % TILES1;
    const int base    = split * CAND;

    // load this split's candidate positions (16B-aligned: 3*1024 floats offset)
    {
        const float4* gp = (const float4*)(pos + ((size_t)b*PPTS + base)*3);
        #pragma unroll
        for (int i = tid; i < 3*CAND/4; i += T1) ((float4*)sp)[i] = gp[i];
    }

    const int ql = tile*T1 + tid;                // query local index in graph
    const float* qp = pos + ((size_t)b*PPTS + ql)*3;
    const float qx = __ldg(qp+0), qy = __ldg(qp+1), qz = __ldg(qp+2);
    __syncthreads();

    u32 bd[KNN];
    #pragma unroll
    for (int s=0;s<KNN;s++) bd[s] = 0xFFFFFFFFu;
    const int selfT = ql - base;                 // only matches when ql in this split

    #pragma unroll 4
    for (int t = 0; t < CAND; ++t) {
        float dx = sp[3*t+0]-qx, dy = sp[3*t+1]-qy, dz = sp[3*t+2]-qz;
        float d  = fmaf(dx,dx,fmaf(dy,dy,dz*dz));
        u32 key = (__float_as_uint(d) & 0xFFFFF000u) | (u32)(base + t);
        if (t == selfT) key = 0xFFFFFFFFu;
        if (key < bd[KNN-1]) {
            u32 c = key;
            #pragma unroll
            for (int s=0;s<KNN;s++){
                u32 lo = min(bd[s], c);
                c = max(bd[s], c);
                bd[s] = lo;
            }
        }
    }

    u32* outp = g_part + ((size_t)tileblk*NSPLIT + split)*(KNN*T1);
    #pragma unroll
    for (int s=0;s<KNN;s++) outp[s*T1 + tid] = bd[s];   // coalesced
}

// ============ kernel 1: merge + cov + eig + dirc + SplineConv + BN partials ============
__global__ __launch_bounds__(T1)
void k1_geom(const float* __restrict__ pos,
             const float* __restrict__ Wsp,
             const float* __restrict__ root,
             const float* __restrict__ bias)
{
    extern __shared__ float sp[];           // 48KB graph positions
    const int tid  = threadIdx.x;
    const int b    = blockIdx.x / TILES1;
    const int tile = blockIdx.x % TILES1;

    {
        const float4* gp = (const float4*)(pos + (size_t)b*PPTS*3);
        for (int i = tid; i < PPTS*3/4; i += T1) ((float4*)sp)[i] = gp[i];
    }
    __syncthreads();

    const int ql = tile*T1 + tid;
    const int n  = b*PPTS + ql;
    const float qx = sp[3*ql+0], qy = sp[3*ql+1], qz = sp[3*ql+2];

    // ---- 4-way merge of partial knn lists (keys unique -> exact) ----
    int bi[KNN];
    {
        const u32* L = g_part + (size_t)blockIdx.x*NSPLIT*(KNN*T1);
        int p0=0,p1=0,p2=0,p3=0;
        #pragma unroll
        for (int r=0;r<KNN;r++){
            u32 v0 = L[0*(KNN*T1) + p0*T1 + tid];
            u32 v1 = L[1*(KNN*T1) + p1*T1 + tid];
            u32 v2 = L[2*(KNN*T1) + p2*T1 + tid];
            u32 v3 = L[3*(KNN*T1) + p3*T1 + tid];
            u32 m01 = min(v0,v1), m23 = min(v2,v3);
            u32 mm  = min(m01,m23);
            bi[r] = (int)(mm & 0xFFFu);
            p0 += (v0==mm); p1 += (v1==mm); p2 += (v2==mm); p3 += (v3==mm);
        }
    }

    // ---- covariance of nearest 10 offsets ----
    float cxx=0.f,cxy=0.f,cxz=0.f,cyy=0.f,cyz=0.f,czz=0.f;
    #pragma unroll
    for (int m=0;m<LCOV;m++){
        int j=bi[m];
        float dx=sp[3*j+0]-qx, dy=sp[3*j+1]-qy, dz=sp[3*j+2]-qz;
        cxx=fmaf(dx,dx,cxx); cxy=fmaf(dx,dy,cxy); cxz=fmaf(dx,dz,cxz);
        cyy=fmaf(dy,dy,cyy); cyz=fmaf(dy,dz,cyz); czz=fmaf(dz,dz,czz);
    }

    // ---- eig via power iteration + deflation + cross ----
    float v1x,v1y,v1z,l1, v2x,v2y,v2z,l2;
    power_iter5(cxx,cxy,cxz,cyy,cyz,czz, v1x,v1y,v1z,l1);
    power_iter5(cxx-l1*v1x*v1x, cxy-l1*v1x*v1y, cxz-l1*v1x*v1z,
                cyy-l1*v1y*v1y, cyz-l1*v1y*v1z, czz-l1*v1z*v1z,
                v2x,v2y,v2z,l2);
    float v3x = v1y*v2z - v1z*v2y;
    float v3y = v1z*v2x - v1x*v2z;
    float v3z = v1x*v2y - v1y*v2x;
    {
        float nn = sqrtf(v3x*v3x+v3y*v3y+v3z*v3z) + 1e-12f;
        v3x/=nn; v3y/=nn; v3z/=nn;
    }

    // ---- dirc pass 1: sign + max_abs ----
    float dl0[KNN], dl1[KNN], dl2[KNN];
    float sumz=0.f, mxa=0.f;
    #pragma unroll
    for (int kk=0;kk<KNN;kk++){
        int j=bi[kk];
        float dx=sp[3*j+0]-qx, dy=sp[3*j+1]-qy, dz=sp[3*j+2]-qz;
        float d0 = dx*v1x+dy*v1y+dz*v1z;
        float d1 = dx*v2x+dy*v2y+dz*v2z;
        float d2 = dx*v3x+dy*v3y+dz*v3z;
        dl0[kk]=d0; dl1[kk]=d1; dl2[kk]=d2;
        sumz += d2;
        mxa = fmaxf(mxa, fmaxf(fabsf(d0), fmaxf(fabsf(d1), fabsf(d2))));
    }
    const float sgn = (sumz>0.f)?1.f:((sumz<0.f)?-1.f:0.f);

    // ---- SplineConv (degree-1, open, KS=5) ----
    float msg[FDIM];
    #pragma unroll
    for (int f=0;f<FDIM;f++) msg[f]=0.f;

    for (int kk=0;kk<KNN;kk++){
        float d0 = dl0[kk], d1 = dl1[kk], d2 = dl2[kk]*sgn;
        float p0 = (d0/mxa)*0.5f+0.5f;
        float p1 = (d1/mxa)*0.5f+0.5f;
        float p2 = (d2/mxa)*0.5f+0.5f;
        float u0 = p0*(float)(KSS-1), u1 = p1*(float)(KSS-1), u2 = p2*(float)(KSS-1);
        float f0 = floorf(u0), f1 = floorf(u1), f2 = floorf(u2);
        float r0 = u0-f0, r1 = u1-f1, r2 = u2-f2;
        int i0 = min(max((int)f0,0),KSS-1);
        int i1 = min(max((int)f1,0),KSS-1);
        int i2 = min(max((int)f2,0),KSS-1);
        #pragma unroll
        for (int s=0;s<8;s++){
            float w0 = (s&4)? r0 : 1.f-r0;
            float w1 = (s&2)? r1 : 1.f-r1;
            float w2 = (s&1)? r2 : 1.f-r2;
            float bas = w0*w1*w2;
            int ii0 = min(i0 + ((s>>2)&1), KSS-1);
            int ii1 = min(i1 + ((s>>1)&1), KSS-1);
            int ii2 = min(i2 + (s&1),      KSS-1);
            int flat = (ii0*KSS+ii1)*KSS+ii2;
            const float4* wr = (const float4*)(Wsp + flat*FDIM);
            #pragma unroll
            for (int q=0;q<FDIM/4;q++){
                float4 w = __ldg(&wr[q]);
                msg[4*q+0] = fmaf(bas,w.x,msg[4*q+0]);
                msg[4*q+1] = fmaf(bas,w.y,msg[4*q+1]);
                msg[4*q+2] = fmaf(bas,w.z,msg[4*q+2]);
                msg[4*q+3] = fmaf(bas,w.w,msg[4*q+3]);
            }
        }
    }

    // ---- node features + outputs ----
    float nodef[FDIM];
    #pragma unroll
    for (int f=0;f<FDIM;f++)
        nodef[f] = msg[f]/(float)KNN + __ldg(&root[f]) + __ldg(&bias[f]);

    {
        float4* on = (float4*)(g_node + (size_t)n*FDIM);
        #pragma unroll
        for (int q=0;q<FDIM/4;q++)
            on[q] = make_float4(nodef[4*q],nodef[4*q+1],nodef[4*q+2],nodef[4*q+3]);
        g_nrm[n*3+0]=v3x; g_nrm[n*3+1]=v3y; g_nrm[n*3+2]=v3z;
    }

    // ---- BN partial sums (block reduce; reuse pos smem after barrier) ----
    float ss[FDIM], sq[FDIM];
    #pragma unroll
    for (int f=0;f<FDIM;f++){ ss[f]=nodef[f]; sq[f]=nodef[f]*nodef[f]; }
    #pragma unroll
    for (int f=0;f<FDIM;f++){
        #pragma unroll
        for (int o=16;o>0;o>>=1){
            ss[f] += __shfl_xor_sync(0xffffffffu, ss[f], o);
            sq[f] += __shfl_xor_sync(0xffffffffu, sq[f], o);
        }
    }
    __syncthreads();
    float* sred = sp;
    int wid = tid>>5, lane = tid&31;
    if (lane==0){
        #pragma unroll
        for (int f=0;f<FDIM;f++){ sred[wid*64+f]=ss[f]; sred[wid*64+32+f]=sq[f]; }
    }
    __syncthreads();
    if (tid < 64){
        float a = sred[tid] + sred[64+tid] + sred[128+tid] + sred[192+tid];
        g_bnpart[blockIdx.x*64 + tid] = a;
    }
}

// ============ kernel 2: finalize BN stats ============
__global__ void k_bnfin(const float* __restrict__ gamma, const float* __restrict__ beta)
{
    int f = threadIdx.x;
    if (f >= FDIM) return;
    double s=0.0, q=0.0;
    for (int b=0;b<BLK1;b++){ s += (double)g_bnpart[b*64+f]; q += (double)g_bnpart[b*64+32+f]; }
    float mu  = (float)(s/(double)NTOT);
    float ex2 = (float)(q/(double)NTOT);
    float var = ex2 - mu*mu;
    float sc  = gamma[f]/sqrtf(var + 1e-5f);
    g_bnfin[f]      = sc;
    g_bnfin[32+f]   = beta[f] - mu*sc;
}

// ============ kernel 3: BN apply + sigmoid + grouped mean partials ============
__global__ __launch_bounds__(T2)
void k2_sig()
{
    __shared__ float sred[8*64];
    const int tid = threadIdx.x;
    const int n   = blockIdx.x*T2 + tid;

    float xb[FDIM];
    {
        const float4* np = (const float4*)(g_node + (size_t)n*FDIM);
        #pragma unroll
        for (int q=0;q<FDIM/4;q++){
            float4 w = np[q];
            xb[4*q+0]=w.x; xb[4*q+1]=w.y; xb[4*q+2]=w.z; xb[4*q+3]=w.w;
        }
        #pragma unroll
        for (int f=0;f<FDIM;f++) xb[f] = xb[f]*g_bnfin[f] + g_bnfin[32+f];
    }
    float vv0 = g_nrm[n*3+0], vv1 = g_nrm[n*3+1], vv2 = g_nrm[n*3+2];

    float accA[FDIM], accB[FDIM];
    #pragma unroll
    for (int j=0;j<FDIM;j++){ accA[j]=0.f; accB[j]=0.f; }

    const int base = n*96;
    const int gA   = (blockIdx.x*T2*96) >> 17;
    const int thr  = (gA+1) << 17;

    #pragma unroll
    for (int m=0;m<96;m++){
        const int f = m/3, c = m-3*f, j = m&31;
        float vc = (c==0)? vv0 : ((c==1)? vv1 : vv2);
        float a  = xb[f]*vc;
        // sigmoid(a) = 0.5*tanh(0.5a)+0.5  (single MUFU)
        float y  = fmaf(0.5f, fast_tanh(0.5f*a), 0.5f);
        if (base + m >= thr) accB[j] += y; else accA[j] += y;
    }

    #pragma unroll
    for (int j=0;j<FDIM;j++){
        #pragma unroll
        for (int o=16;o>0;o>>=1){
            accA[j] += __shfl_xor_sync(0xffffffffu, accA[j], o);
            accB[j] += __shfl_xor_sync(0xffffffffu, accB[j], o);
        }
    }
    int wid = tid>>5, lane = tid&31;
    if (lane==0){
        #pragma unroll
        for (int j=0;j<FDIM;j++){ sred[wid*64+j]=accA[j]; sred[wid*64+32+j]=accB[j]; }
    }
    __syncthreads();
    if (tid < 64){
        float a = 0.f;
        #pragma unroll
        for (int w=0;w<8;w++) a += sred[w*64+tid];
        g_yspart[blockIdx.x*64 + tid] = a;
    }
}

// ============ kernel 4: fold partials + MLP + log_softmax (1024 thr) ============
__global__ __launch_bounds__(1024)
void k3_head(const float* __restrict__ W1, const float* __restrict__ b1,
             const float* __restrict__ W2, const float* __restrict__ b2,
             float* __restrict__ out)
{
    __shared__ float ys[NGROUP*FDIM];    // 768
    __shared__ float y1[NGROUP*HID];     // 6144
    __shared__ float zs[NGROUP*NCLS];    // 960
    __shared__ float ls[NGROUP];
    const int tid = threadIdx.x;

    if (tid < NGROUP*FDIM){
        const int g = tid>>5, j = tid&31;
        float s = 0.f;
        for (int bb=0; bb<BLK2; bb++){
            const int gA = (bb*T2*96) >> 17;
            if (gA   == g) s += g_yspart[bb*64 + j];
            if (gA+1 == g) s += g_yspart[bb*64 + 32 + j];
        }
        ys[tid] = s / 4096.f;
    }
    __syncthreads();

    // layer 1: 6144 (g,h) dots of length 32
    for (int idx = tid; idx < NGROUP*HID; idx += 1024){
        const int g = idx>>8, h = idx&255;
        float d = b1[h];
        #pragma unroll
        for (int f=0; f<FDIM; f++) d = fmaf(ys[g*FDIM+f], __ldg(&W1[f*HID+h]), d);
        y1[idx] = (d > 0.f) ? d : expm1f(d);
    }
    __syncthreads();

    // layer 2: 960 dots of length 256 (4 accumulators)
    if (tid < NGROUP*NCLS){
        const int g = tid/NCLS, cc = tid - g*NCLS;
        float a0=0.f,a1=0.f,a2=0.f,a3=0.f;
        #pragma unroll 4
        for (int h=0; h<HID; h+=4){
            a0 = fmaf(y1[g*HID+h+0], __ldg(&W2[(h+0)*NCLS+cc]), a0);
            a1 = fmaf(y1[g*HID+h+1], __ldg(&W2[(h+1)*NCLS+cc]), a1);
            a2 = fmaf(y1[g*HID+h+2], __ldg(&W2[(h+2)*NCLS+cc]), a2);
            a3 = fmaf(y1[g*HID+h+3], __ldg(&W2[(h+3)*NCLS+cc]), a3);
        }
        zs[tid] = b2[cc] + ((a0+a1)+(a2+a3));
    }
    __syncthreads();

    if (tid < NGROUP){
        float m = -CUDART_INF_F;
        for (int cc=0; cc<NCLS; cc++) m = fmaxf(m, zs[tid*NCLS+cc]);
        float s = 0.f;
        for (int cc=0; cc<NCLS; cc++) s += expf(zs[tid*NCLS+cc] - m);
        ls[tid] = m + logf(s);
    }
    __syncthreads();
    if (tid < NGROUP*NCLS)
        out[tid] = zs[tid] - ls[tid/NCLS];
}

// ---------------- launch ----------------
extern "C" void kernel_launch(void* const* d_in, const int* in_sizes, int n_in,
                              void* d_out, int out_size)
{
    const float* pos   = (const float*)d_in[0];
    const float* Wsp   = (const float*)d_in[1];
    const float* root  = (const float*)d_in[2];
    const float* bias  = (const float*)d_in[3];
    const float* gamma = (const float*)d_in[4];
    const float* beta  = (const float*)d_in[5];
    const float* W1    = (const float*)d_in[6];
    const float* b1    = (const float*)d_in[7];
    const float* W2    = (const float*)d_in[8];
    const float* b2    = (const float*)d_in[9];
    float* out = (float*)d_out;

    k_scan<<<BLK1*NSPLIT, T1>>>(pos);
    const size_t smem1 = (size_t)PPTS*3*sizeof(float);   // 48KB, default limit
    k1_geom<<<BLK1, T1, smem1>>>(pos, Wsp, root, bias);
    k_bnfin<<<1, 32>>>(gamma, beta);
    k2_sig<<<BLK2, T2>>>();
    k3_head<<<1, 1024>>>(W1, b1, W2, b2, out);
}

// round 10
// speedup vs baseline: 3.0801x; 1.1010x over previous
#include <cuda_runtime.h>
#include <math.h>
#include <math_constants.h>

typedef unsigned int u32;

#define BGRAPH 8
#define PPTS   4096
#define KNN    20
#define LCOV   10
#define FDIM   32
#define KSS    5
#define NCLS   40
#define NTOT   (BGRAPH*PPTS)      // 32768
#define NGROUP 24
#define HID    256

#define GRID   32                 // cells per dim
#define CELLS  (GRID*GRID*GRID)   // 32768 per graph
#define CHK    64                 // chunks per graph
#define CHP    64                 // points per chunk (4096/64)

#define T1     128
#define BLK1   (NTOT/T1)          // 256 blocks, 32 per graph
#define TILES1 (PPTS/T1)          // 32
#define T2     256
#define BLK2   (NTOT/T2)          // 128

// ---------------- scratch (device globals; no allocation) ----------------
__device__ float  g_node[NTOT*FDIM];
__device__ float  g_nrm [NTOT*3];
__device__ float  g_bnpart[BLK1*64];
__device__ float  g_bnfin[64];
__device__ float  g_yspart[BLK2*64];
__device__ u32    g_knn[NTOT*KNN];            // sorted packed keys per node
__device__ u32    g_code[NTOT];               // morton code per point
__device__ int    g_cellcnt[BGRAPH*CELLS];    // histogram
__device__ int    g_cellfill[BGRAPH*CELLS];   // write cursors
__device__ float4 g_spos[NTOT];               // sorted (x,y,z, bitcast orig local idx)
__device__ float  g_bbox[BGRAPH*CHK*6];       // per-chunk AABB lo3/hi3

// ---------------- helpers ----------------
__device__ __forceinline__ float fast_tanh(float x){
    float y; asm("tanh.approx.f32 %0, %1;" : "=f"(y) : "f"(x)); return y;
}

__device__ __forceinline__ u32 mort5(u32 x){   // spread 5 bits to every 3rd bit
    u32 r = 0;
    #pragma unroll
    for (int i=0;i<5;i++) r |= ((x>>i)&1u) << (3*i);
    return r;
}

__device__ __forceinline__ void power_iter5(
    float a00,float a01,float a02,float a11,float a12,float a22,
    float& vx,float& vy,float& vz,float& lam)
{
    float x=0.57735026919f, y=0.57735026919f, z=0.57735026919f;
    #pragma unroll
    for (int it=0; it<5; ++it){
        float nx = a00*x + a01*y + a02*z;
        float ny = a01*x + a11*y + a12*z;
        float nz = a02*x + a12*y + a22*z;
        float nrm = sqrtf(nx*nx+ny*ny+nz*nz) + 1e-12f;
        x = nx/nrm; y = ny/nrm; z = nz/nrm;
    }
    float mx = a00*x + a01*y + a02*z;
    float my = a01*x + a11*y + a12*z;
    float mz = a02*x + a12*y + a22*z;
    lam = x*mx + y*my + z*mz;
    vx=x; vy=y; vz=z;
}

// ============ prep A: zero histogram ============
__global__ __launch_bounds__(256) void k_zero()
{
    int i = blockIdx.x*256 + threadIdx.x;      // grid sized exactly
    g_cellcnt[i] = 0;
}

// ============ prep B: cell codes + histogram ============
__global__ __launch_bounds__(256) void k_cell(const float* __restrict__ pos)
{
    int n = blockIdx.x*256 + threadIdx.x;
    if (n >= NTOT) return;
    int b = n >> 12;
    float x = pos[n*3+0], y = pos[n*3+1], z = pos[n*3+2];
    const float s = 32.0f/13.0f;               // grid spans [-6.5, 6.5]
    int cx = min(GRID-1, max(0, (int)floorf((x+6.5f)*s)));
    int cy = min(GRID-1, max(0, (int)floorf((y+6.5f)*s)));
    int cz = min(GRID-1, max(0, (int)floorf((z+6.5f)*s)));
    u32 code = (mort5((u32)cx)<<2) | (mort5((u32)cy)<<1) | mort5((u32)cz);
    g_code[n] = code;
    atomicAdd(&g_cellcnt[b*CELLS + (int)code], 1);
}

// ============ prep C: per-graph exclusive scan over 32768 cells ============
__global__ __launch_bounds__(1024) void k_scanex()
{
    __shared__ int ssum[1024];
    const int g = blockIdx.x, t = threadIdx.x;
    const int base = g*CELLS + t*32;
    int loc[32]; int s = 0;
    #pragma unroll
    for (int i=0;i<32;i++){ loc[i] = g_cellcnt[base+i]; s += loc[i]; }
    ssum[t] = s; __syncthreads();
    for (int o=1;o<1024;o<<=1){
        int v = (t>=o)? ssum[t-o] : 0;
        __syncthreads();
        ssum[t] += v;
        __syncthreads();
    }
    int ex = ssum[t] - s;                      // exclusive prefix
    #pragma unroll
    for (int i=0;i<32;i++){ g_cellfill[base+i] = ex; ex += loc[i]; }
}

// ============ prep D: scatter into sorted order ============
__global__ __launch_bounds__(256) void k_scatter(const float* __restrict__ pos)
{
    int n = blockIdx.x*256 + threadIdx.x;
    if (n >= NTOT) return;
    int b = n >> 12, i = n & 4095;
    u32 code = g_code[n];
    int dst = atomicAdd(&g_cellfill[b*CELLS + (int)code], 1);  // within-graph slot
    float x = pos[n*3+0], y = pos[n*3+1], z = pos[n*3+2];
    g_spos[b*PPTS + dst] = make_float4(x, y, z, __int_as_float(i));
}

// ============ prep E: chunk AABBs (one warp per chunk) ============
__global__ __launch_bounds__(256) void k_bbox()
{
    int c    = blockIdx.x*8 + (threadIdx.x>>5);   // 64 blocks * 8 warps = 512 chunks
    int lane = threadIdx.x & 31;
    const float4* cp = g_spos + c*CHP;
    float4 a = cp[lane], q = cp[lane+32];
    float lx = fminf(a.x,q.x), hx = fmaxf(a.x,q.x);
    float ly = fminf(a.y,q.y), hy = fmaxf(a.y,q.y);
    float lz = fminf(a.z,q.z), hz = fmaxf(a.z,q.z);
    #pragma unroll
    for (int o=16;o>0;o>>=1){
        lx = fminf(lx, __shfl_xor_sync(0xffffffffu, lx, o));
        hx = fmaxf(hx, __shfl_xor_sync(0xffffffffu, hx, o));
        ly = fminf(ly, __shfl_xor_sync(0xffffffffu, ly, o));
        hy = fmaxf(hy, __shfl_xor_sync(0xffffffffu, hy, o));
        lz = fminf(lz, __shfl_xor_sync(0xffffffffu, lz, o));
        hz = fmaxf(hz, __shfl_xor_sync(0xffffffffu, hz, o));
    }
    if (lane==0){
        float* o = g_bbox + c*6;
        o[0]=lx; o[1]=ly; o[2]=lz; o[3]=hx; o[4]=hy; o[5]=hz;
    }
}

// ============ kernel: pruned KNN over sorted chunks ============
__global__ __launch_bounds__(T1) void k_scan2()
{
    __shared__ float  sbb[CHK*6];          // this graph's chunk AABBs
    __shared__ float4 scp[4][CHP];         // per-warp staged chunk
    const int tid  = threadIdx.x;
    const int b    = blockIdx.x / TILES1;
    const int tile = blockIdx.x % TILES1;
    const int wid  = tid>>5, lane = tid&31;

    for (int i = tid; i < CHK*6; i += T1) sbb[i] = g_bbox[b*CHK*6 + i];

    const int qs = tile*T1 + tid;          // sorted index of this query
    float4 q = g_spos[b*PPTS + qs];
    const float qx = q.x, qy = q.y, qz = q.z;
    const int qidx = __float_as_int(q.w);
    __syncthreads();

    const int home = tile*2 + (wid>>1);    // warp-uniform home chunk

    u32 bd[KNN];
    #pragma unroll
    for (int s=0;s<KNN;s++) bd[s] = 0xFFFFFFFFu;

    for (int ci = 0; ci < CHK; ++ci) {
        const int c = (home + ci) & (CHK-1);
        // AABB min-distance^2 to query
        const float* bb = sbb + c*6;
        float dx = fmaxf(fmaxf(bb[0]-qx, qx-bb[3]), 0.f);
        float dy = fmaxf(fmaxf(bb[1]-qy, qy-bb[4]), 0.f);
        float dz = fmaxf(fmaxf(bb[2]-qz, qz-bb[5]), 0.f);
        float bm = fmaf(dx,dx, fmaf(dy,dy, dz*dz));
        u32 mb = __float_as_uint(bm) & 0xFFFFF000u;
        bool need = (mb <= bd[KNN-1]);
        if (!__ballot_sync(0xffffffffu, need)) continue;

        // stage chunk into this warp's smem slab
        const float4* cp = g_spos + b*PPTS + c*CHP;
        __syncwarp();
        scp[wid][lane]    = cp[lane];
        scp[wid][lane+32] = cp[lane+32];
        __syncwarp();

        #pragma unroll 4
        for (int t = 0; t < CHP; ++t) {
            float4 p = scp[wid][t];
            float ddx = p.x-qx, ddy = p.y-qy, ddz = p.z-qz;
            float d = fmaf(ddx,ddx, fmaf(ddy,ddy, ddz*ddz));
            int pi = __float_as_int(p.w);
            u32 key = (__float_as_uint(d) & 0xFFFFF000u) | (u32)pi;
            if (pi == qidx) key = 0xFFFFFFFFu;
            if (key < bd[KNN-1]) {
                u32 cc = key;
                #pragma unroll
                for (int s=0;s<KNN;s++){
                    u32 lo = min(bd[s], cc);
                    cc = max(bd[s], cc);
                    bd[s] = lo;
                }
            }
        }
    }

    u32* outp = g_knn + ((size_t)b*PPTS + qidx)*KNN;   // scatter by orig idx
    #pragma unroll
    for (int s=0;s<KNN;s++) outp[s] = bd[s];
}

// ============ kernel 1: cov + eig + dirc + SplineConv + BN partials ============
__global__ __launch_bounds__(T1)
void k1_geom(const float* __restrict__ pos,
             const float* __restrict__ Wsp,
             const float* __restrict__ root,
             const float* __restrict__ bias)
{
    extern __shared__ float sp[];           // 48KB graph positions
    const int tid  = threadIdx.x;
    const int b    = blockIdx.x / TILES1;
    const int tile = blockIdx.x % TILES1;

    {
        const float4* gp = (const float4*)(pos + (size_t)b*PPTS*3);
        for (int i = tid; i < PPTS*3/4; i += T1) ((float4*)sp)[i] = gp[i];
    }
    __syncthreads();

    const int ql = tile*T1 + tid;
    const int n  = b*PPTS + ql;
    const float qx = sp[3*ql+0], qy = sp[3*ql+1], qz = sp[3*ql+2];

    // ---- neighbor indices (sorted ascending by packed key) ----
    int bi[KNN];
    {
        const u32* L = g_knn + (size_t)n*KNN;
        #pragma unroll
        for (int r=0;r<KNN;r++) bi[r] = (int)(L[r] & 0xFFFu);
    }

    // ---- covariance of nearest 10 offsets ----
    float cxx=0.f,cxy=0.f,cxz=0.f,cyy=0.f,cyz=0.f,czz=0.f;
    #pragma unroll
    for (int m=0;m<LCOV;m++){
        int j=bi[m];
        float dx=sp[3*j+0]-qx, dy=sp[3*j+1]-qy, dz=sp[3*j+2]-qz;
        cxx=fmaf(dx,dx,cxx); cxy=fmaf(dx,dy,cxy); cxz=fmaf(dx,dz,cxz);
        cyy=fmaf(dy,dy,cyy); cyz=fmaf(dy,dz,cyz); czz=fmaf(dz,dz,czz);
    }

    // ---- eig via power iteration + deflation + cross ----
    float v1x,v1y,v1z,l1, v2x,v2y,v2z,l2;
    power_iter5(cxx,cxy,cxz,cyy,cyz,czz, v1x,v1y,v1z,l1);
    power_iter5(cxx-l1*v1x*v1x, cxy-l1*v1x*v1y, cxz-l1*v1x*v1z,
                cyy-l1*v1y*v1y, cyz-l1*v1y*v1z, czz-l1*v1z*v1z,
                v2x,v2y,v2z,l2);
    float v3x = v1y*v2z - v1z*v2y;
    float v3y = v1z*v2x - v1x*v2z;
    float v3z = v1x*v2y - v1y*v2x;
    {
        float nn = sqrtf(v3x*v3x+v3y*v3y+v3z*v3z) + 1e-12f;
        v3x/=nn; v3y/=nn; v3z/=nn;
    }

    // ---- dirc pass 1: sign + max_abs ----
    float dl0[KNN], dl1[KNN], dl2[KNN];
    float sumz=0.f, mxa=0.f;
    #pragma unroll
    for (int kk=0;kk<KNN;kk++){
        int j=bi[kk];
        float dx=sp[3*j+0]-qx, dy=sp[3*j+1]-qy, dz=sp[3*j+2]-qz;
        float d0 = dx*v1x+dy*v1y+dz*v1z;
        float d1 = dx*v2x+dy*v2y+dz*v2z;
        float d2 = dx*v3x+dy*v3y+dz*v3z;
        dl0[kk]=d0; dl1[kk]=d1; dl2[kk]=d2;
        sumz += d2;
        mxa = fmaxf(mxa, fmaxf(fabsf(d0), fmaxf(fabsf(d1), fabsf(d2))));
    }
    const float sgn = (sumz>0.f)?1.f:((sumz<0.f)?-1.f:0.f);

    // ---- SplineConv (degree-1, open, KS=5) ----
    float msg[FDIM];
    #pragma unroll
    for (int f=0;f<FDIM;f++) msg[f]=0.f;

    for (int kk=0;kk<KNN;kk++){
        float d0 = dl0[kk], d1 = dl1[kk], d2 = dl2[kk]*sgn;
        float p0 = (d0/mxa)*0.5f+0.5f;
        float p1 = (d1/mxa)*0.5f+0.5f;
        float p2 = (d2/mxa)*0.5f+0.5f;
        float u0 = p0*(float)(KSS-1), u1 = p1*(float)(KSS-1), u2 = p2*(float)(KSS-1);
        float f0 = floorf(u0), f1 = floorf(u1), f2 = floorf(u2);
        float r0 = u0-f0, r1 = u1-f1, r2 = u2-f2;
        int i0 = min(max((int)f0,0),KSS-1);
        int i1 = min(max((int)f1,0),KSS-1);
        int i2 = min(max((int)f2,0),KSS-1);
        #pragma unroll
        for (int s=0;s<8;s++){
            float w0 = (s&4)? r0 : 1.f-r0;
            float w1 = (s&2)? r1 : 1.f-r1;
            float w2 = (s&1)? r2 : 1.f-r2;
            float bas = w0*w1*w2;
            int ii0 = min(i0 + ((s>>2)&1), KSS-1);
            int ii1 = min(i1 + ((s>>1)&1), KSS-1);
            int ii2 = min(i2 + (s&1),      KSS-1);
            int flat = (ii0*KSS+ii1)*KSS+ii2;
            const float4* wr = (const float4*)(Wsp + flat*FDIM);
            #pragma unroll
            for (int q=0;q<FDIM/4;q++){
                float4 w = __ldg(&wr[q]);
                msg[4*q+0] = fmaf(bas,w.x,msg[4*q+0]);
                msg[4*q+1] = fmaf(bas,w.y,msg[4*q+1]);
                msg[4*q+2] = fmaf(bas,w.z,msg[4*q+2]);
                msg[4*q+3] = fmaf(bas,w.w,msg[4*q+3]);
            }
        }
    }

    // ---- node features + outputs ----
    float nodef[FDIM];
    #pragma unroll
    for (int f=0;f<FDIM;f++)
        nodef[f] = msg[f]/(float)KNN + __ldg(&root[f]) + __ldg(&bias[f]);

    {
        float4* on = (float4*)(g_node + (size_t)n*FDIM);
        #pragma unroll
        for (int q=0;q<FDIM/4;q++)
            on[q] = make_float4(nodef[4*q],nodef[4*q+1],nodef[4*q+2],nodef[4*q+3]);
        g_nrm[n*3+0]=v3x; g_nrm[n*3+1]=v3y; g_nrm[n*3+2]=v3z;
    }

    // ---- BN partial sums ----
    float ss[FDIM], sq[FDIM];
    #pragma unroll
    for (int f=0;f<FDIM;f++){ ss[f]=nodef[f]; sq[f]=nodef[f]*nodef[f]; }
    #pragma unroll
    for (int f=0;f<FDIM;f++){
        #pragma unroll
        for (int o=16;o>0;o>>=1){
            ss[f] += __shfl_xor_sync(0xffffffffu, ss[f], o);
            sq[f] += __shfl_xor_sync(0xffffffffu, sq[f], o);
        }
    }
    __syncthreads();
    float* sred = sp;
    int wid = tid>>5, lane = tid&31;
    if (lane==0){
        #pragma unroll
        for (int f=0;f<FDIM;f++){ sred[wid*64+f]=ss[f]; sred[wid*64+32+f]=sq[f]; }
    }
    __syncthreads();
    if (tid < 64){
        float a = sred[tid] + sred[64+tid] + sred[128+tid] + sred[192+tid];
        g_bnpart[blockIdx.x*64 + tid] = a;
    }
}

// ============ kernel 2: finalize BN stats ============
__global__ void k_bnfin(const float* __restrict__ gamma, const float* __restrict__ beta)
{
    int f = threadIdx.x;
    if (f >= FDIM) return;
    double s=0.0, q=0.0;
    for (int b=0;b<BLK1;b++){ s += (double)g_bnpart[b*64+f]; q += (double)g_bnpart[b*64+32+f]; }
    float mu  = (float)(s/(double)NTOT);
    float ex2 = (float)(q/(double)NTOT);
    float var = ex2 - mu*mu;
    float sc  = gamma[f]/sqrtf(var + 1e-5f);
    g_bnfin[f]      = sc;
    g_bnfin[32+f]   = beta[f] - mu*sc;
}

// ============ kernel 3: BN apply + sigmoid + grouped mean partials ============
__global__ __launch_bounds__(T2)
void k2_sig()
{
    __shared__ float sred[8*64];
    const int tid = threadIdx.x;
    const int n   = blockIdx.x*T2 + tid;

    float xb[FDIM];
    {
        const float4* np = (const float4*)(g_node + (size_t)n*FDIM);
        #pragma unroll
        for (int q=0;q<FDIM/4;q++){
            float4 w = np[q];
            xb[4*q+0]=w.x; xb[4*q+1]=w.y; xb[4*q+2]=w.z; xb[4*q+3]=w.w;
        }
        #pragma unroll
        for (int f=0;f<FDIM;f++) xb[f] = xb[f]*g_bnfin[f] + g_bnfin[32+f];
    }
    float vv0 = g_nrm[n*3+0], vv1 = g_nrm[n*3+1], vv2 = g_nrm[n*3+2];

    float accA[FDIM], accB[FDIM];
    #pragma unroll
    for (int j=0;j<FDIM;j++){ accA[j]=0.f; accB[j]=0.f; }

    const int base = n*96;
    const int gA   = (blockIdx.x*T2*96) >> 17;
    const int thr  = (gA+1) << 17;

    #pragma unroll
    for (int m=0;m<96;m++){
        const int f = m/3, c = m-3*f, j = m&31;
        float vc = (c==0)? vv0 : ((c==1)? vv1 : vv2);
        float a  = xb[f]*vc;
        float y  = fmaf(0.5f, fast_tanh(0.5f*a), 0.5f);
        if (base + m >= thr) accB[j] += y; else accA[j] += y;
    }

    #pragma unroll
    for (int j=0;j<FDIM;j++){
        #pragma unroll
        for (int o=16;o>0;o>>=1){
            accA[j] += __shfl_xor_sync(0xffffffffu, accA[j], o);
            accB[j] += __shfl_xor_sync(0xffffffffu, accB[j], o);
        }
    }
    int wid = tid>>5, lane = tid&31;
    if (lane==0){
        #pragma unroll
        for (int j=0;j<FDIM;j++){ sred[wid*64+j]=accA[j]; sred[wid*64+32+j]=accB[j]; }
    }
    __syncthreads();
    if (tid < 64){
        float a = 0.f;
        #pragma unroll
        for (int w=0;w<8;w++) a += sred[w*64+tid];
        g_yspart[blockIdx.x*64 + tid] = a;
    }
}

// ============ kernel 4: fold partials + MLP + log_softmax ============
__global__ __launch_bounds__(1024)
void k3_head(const float* __restrict__ W1, const float* __restrict__ b1,
             const float* __restrict__ W2, const float* __restrict__ b2,
             float* __restrict__ out)
{
    __shared__ float ys[NGROUP*FDIM];
    __shared__ float y1[NGROUP*HID];
    __shared__ float zs[NGROUP*NCLS];
    __shared__ float ls[NGROUP];
    const int tid = threadIdx.x;

    if (tid < NGROUP*FDIM){
        const int g = tid>>5, j = tid&31;
        float s = 0.f;
        for (int bb=0; bb<BLK2; bb++){
            const int gA = (bb*T2*96) >> 17;
            if (gA   == g) s += g_yspart[bb*64 + j];
            if (gA+1 == g) s += g_yspart[bb*64 + 32 + j];
        }
        ys[tid] = s / 4096.f;
    }
    __syncthreads();

    for (int idx = tid; idx < NGROUP*HID; idx += 1024){
        const int g = idx>>8, h = idx&255;
        float d = b1[h];
        #pragma unroll
        for (int f=0; f<FDIM; f++) d = fmaf(ys[g*FDIM+f], __ldg(&W1[f*HID+h]), d);
        y1[idx] = (d > 0.f) ? d : expm1f(d);
    }
    __syncthreads();

    if (tid < NGROUP*NCLS){
        const int g = tid/NCLS, cc = tid - g*NCLS;
        float a0=0.f,a1=0.f,a2=0.f,a3=0.f;
        #pragma unroll 4
        for (int h=0; h<HID; h+=4){
            a0 = fmaf(y1[g*HID+h+0], __ldg(&W2[(h+0)*NCLS+cc]), a0);
            a1 = fmaf(y1[g*HID+h+1], __ldg(&W2[(h+1)*NCLS+cc]), a1);
            a2 = fmaf(y1[g*HID+h+2], __ldg(&W2[(h+2)*NCLS+cc]), a2);
            a3 = fmaf(y1[g*HID+h+3], __ldg(&W2[(h+3)*NCLS+cc]), a3);
        }
        zs[tid] = b2[cc] + ((a0+a1)+(a2+a3));
    }
    __syncthreads();

    if (tid < NGROUP){
        float m = -CUDART_INF_F;
        for (int cc=0; cc<NCLS; cc++) m = fmaxf(m, zs[tid*NCLS+cc]);
        float s = 0.f;
        for (int cc=0; cc<NCLS; cc++) s += expf(zs[tid*NCLS+cc] - m);
        ls[tid] = m + logf(s);
    }
    __syncthreads();
    if (tid < NGROUP*NCLS)
        out[tid] = zs[tid] - ls[tid/NCLS];
}

// ---------------- launch ----------------
extern "C" void kernel_launch(void* const* d_in, const int* in_sizes, int n_in,
                              void* d_out, int out_size)
{
    const float* pos   = (const float*)d_in[0];
    const float* Wsp   = (const float*)d_in[1];
    const float* root  = (const float*)d_in[2];
    const float* bias  = (const float*)d_in[3];
    const float* gamma = (const float*)d_in[4];
    const float* beta  = (const float*)d_in[5];
    const float* W1    = (const float*)d_in[6];
    const float* b1    = (const float*)d_in[7];
    const float* W2    = (const float*)d_in[8];
    const float* b2    = (const float*)d_in[9];
    float* out = (float*)d_out;

    k_zero   <<<(BGRAPH*CELLS)/256, 256>>>();
    k_cell   <<<NTOT/256, 256>>>(pos);
    k_scanex <<<BGRAPH, 1024>>>();
    k_scatter<<<NTOT/256, 256>>>(pos);
    k_bbox   <<<(BGRAPH*CHK)/8, 256>>>();
    k_scan2  <<<BLK1, T1>>>();
    const size_t smem1 = (size_t)PPTS*3*sizeof(float);   // 48KB, default limit
    k1_geom  <<<BLK1, T1, smem1>>>(pos, Wsp, root, bias);
    k_bnfin  <<<1, 32>>>(gamma, beta);
    k2_sig   <<<BLK2, T2>>>();
    k3_head  <<<1, 1024>>>(W1, b1, W2, b2, out);
}

// round 13
// speedup vs baseline: 4.6983x; 1.5254x over previous
#include <cuda_runtime.h>
#include <math.h>
#include <math_constants.h>

typedef unsigned int u32;

#define BGRAPH 8
#define PPTS   4096
#define KNN    20
#define LCOV   10
#define FDIM   32
#define KSS    5
#define NCLS   40
#define NTOT   (BGRAPH*PPTS)      // 32768
#define NGROUP 24
#define HID    256

#define GRID   32                 // cells per dim
#define CELLS  (GRID*GRID*GRID)   // 32768 per graph
#define CHK    64                 // chunks per graph
#define CHP    64                 // points per chunk (4096/64)

#define T1     128
#define BLK1   (NTOT/T1)          // 256 blocks, 32 per graph
#define TILES1 (PPTS/T1)          // 32
#define T2     256
#define BLK2   (NTOT/T2)          // 128

// ---------------- scratch (device globals; no allocation) ----------------
__device__ float  g_node[NTOT*FDIM];
__device__ float  g_nrm [NTOT*3];
__device__ float  g_bnpart[BLK1*64];
__device__ float  g_bnfin[64];
__device__ float  g_yspart[BLK2*64];
__device__ u32    g_knn[BGRAPH*KNN*PPTS];     // keys, layout [graph][s][sorted_idx]
__device__ u32    g_code[NTOT];               // morton code per point
__device__ int    g_cellcnt[BGRAPH*CELLS];    // histogram
__device__ int    g_cellfill[BGRAPH*CELLS];   // write cursors
__device__ float4 g_spos[NTOT];               // sorted (x,y,z, bitcast orig local idx)
__device__ float  g_bbox[BGRAPH*CHK*6];       // per-chunk AABB lo3/hi3

// ---------------- helpers ----------------
__device__ __forceinline__ float fast_tanh(float x){
    float y; asm("tanh.approx.f32 %0, %1;" : "=f"(y) : "f"(x)); return y;
}

__device__ __forceinline__ u32 mort5(u32 x){
    u32 r = 0;
    #pragma unroll
    for (int i=0;i<5;i++) r |= ((x>>i)&1u) << (3*i);
    return r;
}

__device__ __forceinline__ void power_iter5(
    float a00,float a01,float a02,float a11,float a12,float a22,
    float& vx,float& vy,float& vz,float& lam)
{
    float x=0.57735026919f, y=0.57735026919f, z=0.57735026919f;
    #pragma unroll
    for (int it=0; it<5; ++it){
        float nx = a00*x + a01*y + a02*z;
        float ny = a01*x + a11*y + a12*z;
        float nz = a02*x + a12*y + a22*z;
        float nrm = sqrtf(nx*nx+ny*ny+nz*nz) + 1e-12f;
        x = nx/nrm; y = ny/nrm; z = nz/nrm;
    }
    float mx = a00*x + a01*y + a02*z;
    float my = a01*x + a11*y + a12*z;
    float mz = a02*x + a12*y + a22*z;
    lam = x*mx + y*my + z*mz;
    vx=x; vy=y; vz=z;
}

// ============ prep A: zero histogram ============
__global__ __launch_bounds__(256) void k_zero()
{
    int i = blockIdx.x*256 + threadIdx.x;
    g_cellcnt[i] = 0;
}

// ============ prep B: cell codes + histogram ============
__global__ __launch_bounds__(256) void k_cell(const float* __restrict__ pos)
{
    int n = blockIdx.x*256 + threadIdx.x;
    if (n >= NTOT) return;
    int b = n >> 12;
    float x = pos[n*3+0], y = pos[n*3+1], z = pos[n*3+2];
    const float s = 32.0f/13.0f;               // grid spans [-6.5, 6.5]
    int cx = min(GRID-1, max(0, (int)floorf((x+6.5f)*s)));
    int cy = min(GRID-1, max(0, (int)floorf((y+6.5f)*s)));
    int cz = min(GRID-1, max(0, (int)floorf((z+6.5f)*s)));
    u32 code = (mort5((u32)cx)<<2) | (mort5((u32)cy)<<1) | mort5((u32)cz);
    g_code[n] = code;
    atomicAdd(&g_cellcnt[b*CELLS + (int)code], 1);
}

// ============ prep C: per-graph exclusive scan over 32768 cells ============
__global__ __launch_bounds__(1024) void k_scanex()
{
    __shared__ int ssum[1024];
    const int g = blockIdx.x, t = threadIdx.x;
    const int base = g*CELLS + t*32;
    int loc[32]; int s = 0;
    #pragma unroll
    for (int i=0;i<32;i++){ loc[i] = g_cellcnt[base+i]; s += loc[i]; }
    ssum[t] = s; __syncthreads();
    for (int o=1;o<1024;o<<=1){
        int v = (t>=o)? ssum[t-o] : 0;
        __syncthreads();
        ssum[t] += v;
        __syncthreads();
    }
    int ex = ssum[t] - s;
    #pragma unroll
    for (int i=0;i<32;i++){ g_cellfill[base+i] = ex; ex += loc[i]; }
}

// ============ prep D: scatter into sorted order ============
__global__ __launch_bounds__(256) void k_scatter(const float* __restrict__ pos)
{
    int n = blockIdx.x*256 + threadIdx.x;
    if (n >= NTOT) return;
    int b = n >> 12, i = n & 4095;
    u32 code = g_code[n];
    int dst = atomicAdd(&g_cellfill[b*CELLS + (int)code], 1);
    float x = pos[n*3+0], y = pos[n*3+1], z = pos[n*3+2];
    g_spos[b*PPTS + dst] = make_float4(x, y, z, __int_as_float(i));
}

// ============ prep E: chunk AABBs (one warp per chunk) ============
__global__ __launch_bounds__(256) void k_bbox()
{
    int c    = blockIdx.x*8 + (threadIdx.x>>5);
    int lane = threadIdx.x & 31;
    const float4* cp = g_spos + c*CHP;
    float4 a = cp[lane], q = cp[lane+32];
    float lx = fminf(a.x,q.x), hx = fmaxf(a.x,q.x);
    float ly = fminf(a.y,q.y), hy = fmaxf(a.y,q.y);
    float lz = fminf(a.z,q.z), hz = fmaxf(a.z,q.z);
    #pragma unroll
    for (int o=16;o>0;o>>=1){
        lx = fminf(lx, __shfl_xor_sync(0xffffffffu, lx, o));
        hx = fmaxf(hx, __shfl_xor_sync(0xffffffffu, hx, o));
        ly = fminf(ly, __shfl_xor_sync(0xffffffffu, ly, o));
        hy = fmaxf(hy, __shfl_xor_sync(0xffffffffu, hy, o));
        lz = fminf(lz, __shfl_xor_sync(0xffffffffu, lz, o));
        hz = fmaxf(hz, __shfl_xor_sync(0xffffffffu, hz, o));
    }
    if (lane==0){
        float* o = g_bbox + c*6;
        o[0]=lx; o[1]=ly; o[2]=lz; o[3]=hx; o[4]=hy; o[5]=hz;
    }
}

// ============ kernel: pruned KNN over sorted chunks (keys carry SORTED idx) ============
__global__ __launch_bounds__(T1) void k_scan2()
{
    __shared__ float  sbb[CHK*6];
    __shared__ float4 scp[4][CHP];
    const int tid  = threadIdx.x;
    const int b    = blockIdx.x / TILES1;
    const int tile = blockIdx.x % TILES1;
    const int wid  = tid>>5, lane = tid&31;

    for (int i = tid; i < CHK*6; i += T1) sbb[i] = g_bbox[b*CHK*6 + i];

    const int qs = tile*T1 + tid;          // sorted index of this query
    float4 q = g_spos[b*PPTS + qs];
    const float qx = q.x, qy = q.y, qz = q.z;
    __syncthreads();

    const int home = tile*2 + (wid>>1);

    u32 bd[KNN];
    #pragma unroll
    for (int s=0;s<KNN;s++) bd[s] = 0xFFFFFFFFu;

    for (int ci = 0; ci < CHK; ++ci) {
        const int c = (home + ci) & (CHK-1);
        const float* bb = sbb + c*6;
        float dx = fmaxf(fmaxf(bb[0]-qx, qx-bb[3]), 0.f);
        float dy = fmaxf(fmaxf(bb[1]-qy, qy-bb[4]), 0.f);
        float dz = fmaxf(fmaxf(bb[2]-qz, qz-bb[5]), 0.f);
        float bm = fmaf(dx,dx, fmaf(dy,dy, dz*dz));
        u32 mb = __float_as_uint(bm) & 0xFFFFF000u;
        bool need = (mb <= bd[KNN-1]);
        if (!__ballot_sync(0xffffffffu, need)) continue;

        const float4* cp = g_spos + b*PPTS + c*CHP;
        __syncwarp();
        scp[wid][lane]    = cp[lane];
        scp[wid][lane+32] = cp[lane+32];
        __syncwarp();

        const int cbase = c*CHP;
        #pragma unroll 4
        for (int t = 0; t < CHP; ++t) {
            float4 p = scp[wid][t];
            float ddx = p.x-qx, ddy = p.y-qy, ddz = p.z-qz;
            float d = fmaf(ddx,ddx, fmaf(ddy,ddy, ddz*ddz));
            int si = cbase + t;                         // sorted index
            u32 key = (__float_as_uint(d) & 0xFFFFF000u) | (u32)si;
            if (si == qs) key = 0xFFFFFFFFu;
            if (key < bd[KNN-1]) {
                u32 cc = key;
                #pragma unroll
                for (int s=0;s<KNN;s++){
                    u32 lo = min(bd[s], cc);
                    cc = max(bd[s], cc);
                    bd[s] = lo;
                }
            }
        }
    }

    // transposed store: [graph][s][sorted_idx] -> fully coalesced both sides
    u32* outp = g_knn + (size_t)b*KNN*PPTS + qs;
    #pragma unroll
    for (int s=0;s<KNN;s++) outp[s*PPTS] = bd[s];
}

// ============ kernel 1: cov + eig + dirc + SplineConv + BN partials ============
// Sorted-order threads; Wsp cached in smem (padded rows); no big register arrays.
__global__ __launch_bounds__(T1)
void k1_geom(const float* __restrict__ Wsp,
             const float* __restrict__ root,
             const float* __restrict__ bias)
{
    __shared__ float4 swsp[125*9];          // row stride 9 float4 (36 floats) -> bank spread
    __shared__ float  sred[4*64];
    const int tid = threadIdx.x;
    const int b   = blockIdx.x / TILES1;
    const int tile= blockIdx.x % TILES1;

    // cooperative Wsp load (125 rows x 8 float4)
    {
        const float4* wsrc = (const float4*)Wsp;
        for (int i = tid; i < 125*8; i += T1){
            int fl = i>>3, qq = i&7;
            swsp[fl*9+qq] = wsrc[fl*8+qq];
        }
    }

    const int qs = tile*T1 + tid;              // sorted index
    const float4 qrec = g_spos[(size_t)b*PPTS + qs];
    const float qx = qrec.x, qy = qrec.y, qz = qrec.z;
    const int qidx = __float_as_int(qrec.w);   // original local index
    const int n = b*PPTS + qidx;
    const u32* KL = g_knn + (size_t)b*KNN*PPTS + qs;   // key list, stride PPTS
    const float4* SP = g_spos + (size_t)b*PPTS;
    __syncthreads();

    // ---- pass 1: covariance of nearest 10 offsets ----
    float cxx=0.f,cxy=0.f,cxz=0.f,cyy=0.f,cyz=0.f,czz=0.f;
    for (int m=0;m<LCOV;m++){
        int j = (int)(KL[m*PPTS] & 0xFFFu);
        float4 p = SP[j];
        float dx=p.x-qx, dy=p.y-qy, dz=p.z-qz;
        cxx=fmaf(dx,dx,cxx); cxy=fmaf(dx,dy,cxy); cxz=fmaf(dx,dz,cxz);
        cyy=fmaf(dy,dy,cyy); cyz=fmaf(dy,dz,cyz); czz=fmaf(dz,dz,czz);
    }

    // ---- eig via power iteration + deflation + cross ----
    float v1x,v1y,v1z,l1, v2x,v2y,v2z,l2;
    power_iter5(cxx,cxy,cxz,cyy,cyz,czz, v1x,v1y,v1z,l1);
    power_iter5(cxx-l1*v1x*v1x, cxy-l1*v1x*v1y, cxz-l1*v1x*v1z,
                cyy-l1*v1y*v1y, cyz-l1*v1y*v1z, czz-l1*v1z*v1z,
                v2x,v2y,v2z,l2);
    float v3x = v1y*v2z - v1z*v2y;
    float v3y = v1z*v2x - v1x*v2z;
    float v3z = v1x*v2y - v1y*v2x;
    {
        float nn = sqrtf(v3x*v3x+v3y*v3y+v3z*v3z) + 1e-12f;
        v3x/=nn; v3y/=nn; v3z/=nn;
    }

    // ---- pass 2: sign + max_abs over 20 rotated offsets ----
    float sumz=0.f, mxa=0.f;
    for (int kk=0;kk<KNN;kk++){
        int j = (int)(KL[kk*PPTS] & 0xFFFu);
        float4 p = SP[j];
        float dx=p.x-qx, dy=p.y-qy, dz=p.z-qz;
        float d0 = dx*v1x+dy*v1y+dz*v1z;
        float d1 = dx*v2x+dy*v2y+dz*v2z;
        float d2 = dx*v3x+dy*v3y+dz*v3z;
        sumz += d2;
        mxa = fmaxf(mxa, fmaxf(fabsf(d0), fmaxf(fabsf(d1), fabsf(d2))));
    }
    const float sgn = (sumz>0.f)?1.f:((sumz<0.f)?-1.f:0.f);
    const float inv = 0.5f/mxa;

    // ---- pass 3: SplineConv (degree-1, open, KS=5), Wsp from smem ----
    float msg[FDIM];
    #pragma unroll
    for (int f=0;f<FDIM;f++) msg[f]=0.f;

    for (int kk=0;kk<KNN;kk++){
        int j = (int)(KL[kk*PPTS] & 0xFFFu);
        float4 p = SP[j];
        float dx=p.x-qx, dy=p.y-qy, dz=p.z-qz;
        float d0 = dx*v1x+dy*v1y+dz*v1z;
        float d1 = dx*v2x+dy*v2y+dz*v2z;
        float d2 = (dx*v3x+dy*v3y+dz*v3z)*sgn;
        float p0 = fmaf(d0, inv, 0.5f);
        float p1 = fmaf(d1, inv, 0.5f);
        float p2 = fmaf(d2, inv, 0.5f);
        float u0 = p0*(float)(KSS-1), u1 = p1*(float)(KSS-1), u2 = p2*(float)(KSS-1);
        float f0 = floorf(u0), f1 = floorf(u1), f2 = floorf(u2);
        float r0 = u0-f0, r1 = u1-f1, r2 = u2-f2;
        int i0 = min(max((int)f0,0),KSS-1);
        int i1 = min(max((int)f1,0),KSS-1);
        int i2 = min(max((int)f2,0),KSS-1);
        #pragma unroll
        for (int s=0;s<8;s++){
            float w0 = (s&4)? r0 : 1.f-r0;
            float w1 = (s&2)? r1 : 1.f-r1;
            float w2 = (s&1)? r2 : 1.f-r2;
            float bas = w0*w1*w2;
            int ii0 = min(i0 + ((s>>2)&1), KSS-1);
            int ii1 = min(i1 + ((s>>1)&1), KSS-1);
            int ii2 = min(i2 + (s&1),      KSS-1);
            int flat = (ii0*KSS+ii1)*KSS+ii2;
            const float4* wr = swsp + flat*9;
            #pragma unroll
            for (int q=0;q<FDIM/4;q++){
                float4 w = wr[q];
                msg[4*q+0] = fmaf(bas,w.x,msg[4*q+0]);
                msg[4*q+1] = fmaf(bas,w.y,msg[4*q+1]);
                msg[4*q+2] = fmaf(bas,w.z,msg[4*q+2]);
                msg[4*q+3] = fmaf(bas,w.w,msg[4*q+3]);
            }
        }
    }

    // ---- node features + outputs (scatter by original idx) ----
    float nodef[FDIM];
    #pragma unroll
    for (int f=0;f<FDIM;f++)
        nodef[f] = msg[f]/(float)KNN + __ldg(&root[f]) + __ldg(&bias[f]);

    {
        float4* on = (float4*)(g_node + (size_t)n*FDIM);
        #pragma unroll
        for (int q=0;q<FDIM/4;q++)
            on[q] = make_float4(nodef[4*q],nodef[4*q+1],nodef[4*q+2],nodef[4*q+3]);
        g_nrm[n*3+0]=v3x; g_nrm[n*3+1]=v3y; g_nrm[n*3+2]=v3z;
    }

    // ---- BN partial sums ----
    float ss[FDIM], sq[FDIM];
    #pragma unroll
    for (int f=0;f<FDIM;f++){ ss[f]=nodef[f]; sq[f]=nodef[f]*nodef[f]; }
    #pragma unroll
    for (int f=0;f<FDIM;f++){
        #pragma unroll
        for (int o=16;o>0;o>>=1){
            ss[f] += __shfl_xor_sync(0xffffffffu, ss[f], o);
            sq[f] += __shfl_xor_sync(0xffffffffu, sq[f], o);
        }
    }
    int wid = tid>>5, lane = tid&31;
    if (lane==0){
        #pragma unroll
        for (int f=0;f<FDIM;f++){ sred[wid*64+f]=ss[f]; sred[wid*64+32+f]=sq[f]; }
    }
    __syncthreads();
    if (tid < 64){
        float a = sred[tid] + sred[64+tid] + sred[128+tid] + sred[192+tid];
        g_bnpart[blockIdx.x*64 + tid] = a;
    }
}

// ============ kernel 2: finalize BN stats (256 thr, deterministic order) ============
__global__ __launch_bounds__(256)
void k_bnfin(const float* __restrict__ gamma, const float* __restrict__ beta)
{
    __shared__ double shS[256], shQ[256];
    const int t = threadIdx.x;
    const int f = t & 31, p = t >> 5;          // 8 partials per feature
    double s=0.0, q=0.0;
    for (int b=p*32; b<p*32+32; b++){
        s += (double)g_bnpart[b*64+f];
        q += (double)g_bnpart[b*64+32+f];
    }
    shS[t]=s; shQ[t]=q;
    __syncthreads();
    if (p == 0){
        double ts=0.0, tq=0.0;
        #pragma unroll
        for (int pp=0; pp<8; pp++){ ts += shS[pp*32+f]; tq += shQ[pp*32+f]; }
        float mu  = (float)(ts/(double)NTOT);
        float ex2 = (float)(tq/(double)NTOT);
        float var = ex2 - mu*mu;
        float sc  = gamma[f]/sqrtf(var + 1e-5f);
        g_bnfin[f]    = sc;
        g_bnfin[32+f] = beta[f] - mu*sc;
    }
}

// ============ kernel 3: BN apply + sigmoid + grouped mean partials ============
__global__ __launch_bounds__(T2)
void k2_sig()
{
    __shared__ float sred[8*64];
    const int tid = threadIdx.x;
    const int n   = blockIdx.x*T2 + tid;

    float xb[FDIM];
    {
        const float4* np = (const float4*)(g_node + (size_t)n*FDIM);
        #pragma unroll
        for (int q=0;q<FDIM/4;q++){
            float4 w = np[q];
            xb[4*q+0]=w.x; xb[4*q+1]=w.y; xb[4*q+2]=w.z; xb[4*q+3]=w.w;
        }
        #pragma unroll
        for (int f=0;f<FDIM;f++) xb[f] = xb[f]*g_bnfin[f] + g_bnfin[32+f];
    }
    float vv0 = g_nrm[n*3+0], vv1 = g_nrm[n*3+1], vv2 = g_nrm[n*3+2];

    float accA[FDIM], accB[FDIM];
    #pragma unroll
    for (int j=0;j<FDIM;j++){ accA[j]=0.f; accB[j]=0.f; }

    const int base = n*96;
    const int gA   = (blockIdx.x*T2*96) >> 17;
    const int thr  = (gA+1) << 17;

    #pragma unroll
    for (int m=0;m<96;m++){
        const int f = m/3, c = m-3*f, j = m&31;
        float vc = (c==0)? vv0 : ((c==1)? vv1 : vv2);
        float a  = xb[f]*vc;
        float y  = fmaf(0.5f, fast_tanh(0.5f*a), 0.5f);
        if (base + m >= thr) accB[j] += y; else accA[j] += y;
    }

    #pragma unroll
    for (int j=0;j<FDIM;j++){
        #pragma unroll
        for (int o=16;o>0;o>>=1){
            accA[j] += __shfl_xor_sync(0xffffffffu, accA[j], o);
            accB[j] += __shfl_xor_sync(0xffffffffu, accB[j], o);
        }
    }
    int wid = tid>>5, lane = tid&31;
    if (lane==0){
        #pragma unroll
        for (int j=0;j<FDIM;j++){ sred[wid*64+j]=accA[j]; sred[wid*64+32+j]=accB[j]; }
    }
    __syncthreads();
    if (tid < 64){
        float a = 0.f;
        #pragma unroll
        for (int w=0;w<8;w++) a += sred[w*64+tid];
        g_yspart[blockIdx.x*64 + tid] = a;
    }
}

// ============ kernel 4: fold partials + MLP + log_softmax ============
__global__ __launch_bounds__(1024)
void k3_head(const float* __restrict__ W1, const float* __restrict__ b1,
             const float* __restrict__ W2, const float* __restrict__ b2,
             float* __restrict__ out)
{
    __shared__ float ys[NGROUP*FDIM];
    __shared__ float y1[NGROUP*HID];
    __shared__ float zs[NGROUP*NCLS];
    __shared__ float ls[NGROUP];
    const int tid = threadIdx.x;

    if (tid < NGROUP*FDIM){
        const int g = tid>>5, j = tid&31;
        float s = 0.f;
        for (int bb=0; bb<BLK2; bb++){
            const int gA = (bb*T2*96) >> 17;
            if (gA   == g) s += g_yspart[bb*64 + j];
            if (gA+1 == g) s += g_yspart[bb*64 + 32 + j];
        }
        ys[tid] = s / 4096.f;
    }
    __syncthreads();

    for (int idx = tid; idx < NGROUP*HID; idx += 1024){
        const int g = idx>>8, h = idx&255;
        float d = b1[h];
        #pragma unroll
        for (int f=0; f<FDIM; f++) d = fmaf(ys[g*FDIM+f], __ldg(&W1[f*HID+h]), d);
        y1[idx] = (d > 0.f) ? d : expm1f(d);
    }
    __syncthreads();

    if (tid < NGROUP*NCLS){
        const int g = tid/NCLS, cc = tid - g*NCLS;
        float a0=0.f,a1=0.f,a2=0.f,a3=0.f;
        #pragma unroll 4
        for (int h=0; h<HID; h+=4){
            a0 = fmaf(y1[g*HID+h+0], __ldg(&W2[(h+0)*NCLS+cc]), a0);
            a1 = fmaf(y1[g*HID+h+1], __ldg(&W2[(h+1)*NCLS+cc]), a1);
            a2 = fmaf(y1[g*HID+h+2], __ldg(&W2[(h+2)*NCLS+cc]), a2);
            a3 = fmaf(y1[g*HID+h+3], __ldg(&W2[(h+3)*NCLS+cc]), a3);
        }
        zs[tid] = b2[cc] + ((a0+a1)+(a2+a3));
    }
    __syncthreads();

    if (tid < NGROUP){
        float m = -CUDART_INF_F;
        for (int cc=0; cc<NCLS; cc++) m = fmaxf(m, zs[tid*NCLS+cc]);
        float s = 0.f;
        for (int cc=0; cc<NCLS; cc++) s += expf(zs[tid*NCLS+cc] - m);
        ls[tid] = m + logf(s);
    }
    __syncthreads();
    if (tid < NGROUP*NCLS)
        out[tid] = zs[tid] - ls[tid/NCLS];
}

// ---------------- launch ----------------
extern "C" void kernel_launch(void* const* d_in, const int* in_sizes, int n_in,
                              void* d_out, int out_size)
{
    const float* pos   = (const float*)d_in[0];
    const float* Wsp   = (const float*)d_in[1];
    const float* root  = (const float*)d_in[2];
    const float* bias  = (const float*)d_in[3];
    const float* gamma = (const float*)d_in[4];
    const float* beta  = (const float*)d_in[5];
    const float* W1    = (const float*)d_in[6];
    const float* b1    = (const float*)d_in[7];
    const float* W2    = (const float*)d_in[8];
    const float* b2    = (const float*)d_in[9];
    float* out = (float*)d_out;

    k_zero   <<<(BGRAPH*CELLS)/256, 256>>>();
    k_cell   <<<NTOT/256, 256>>>(pos);
    k_scanex <<<BGRAPH, 1024>>>();
    k_scatter<<<NTOT/256, 256>>>(pos);
    k_bbox   <<<(BGRAPH*CHK)/8, 256>>>();
    k_scan2  <<<BLK1, T1>>>();
    k1_geom  <<<BLK1, T1>>>(Wsp, root, bias);
    k_bnfin  <<<1, 256>>>(gamma, beta);
    k2_sig   <<<BLK2, T2>>>();
    k3_head  <<<1, 1024>>>(W1, b1, W2, b2, out);
}